// round 11
// baseline (speedup 1.0000x reference)
#include <cuda_runtime.h>

#define NN 100000
#define EE 1600000
#define DD 64
#define HH 64
#define GG 64
#define CC 2

// ---- scratch (device globals; referenced ONLY inside device code) ----
__device__ __align__(16) float d_hbuf[NN * HH];
__device__ __align__(16) float d_gbuf[NN * HH];
__device__ __align__(16) float d_accbuf[NN * HH];
__device__ float d_deg[NN];
__device__ float d_sums[GG * HH];
__device__ float d_cnts[GG];

// ---------------------------------------------------------------------------
__global__ void k_zero_deg() {
    int i = blockIdx.x * blockDim.x + threadIdx.x;
    if (i < NN) d_deg[i] = 0.0f;
}

__global__ void k_deg(const int* __restrict__ edge_index) {
    int e = blockIdx.x * blockDim.x + threadIdx.x;
    if (e < EE) {
        int dst = edge_index[EE + e];
        if ((unsigned)dst < NN) atomicAdd(&d_deg[dst], 1.0f);
    }
}

// ---------------------------------------------------------------------------
// g[row] = (X[row] @ W) * rsqrt(deg+1);  acc[row] = g[row]  (self-loop seed)
// FROM_HBUF: read input from device-global d_hbuf inside device code
// (passing the global as a host-side kernel arg gives the host shadow
// address — silently readable via ATS on GB300, and all zeros).
template <bool FROM_HBUF>
__global__ void k_gemm(const float* __restrict__ Xext, const float* __restrict__ W) {
    const float* X = FROM_HBUF ? (const float*)d_hbuf : Xext;

    __shared__ float Ws[64 * 64];
    __shared__ float Xs[16][64];

    int tid = threadIdx.x;
    int tx = tid & 63;
    int ty = tid >> 6;
    int row0 = blockIdx.x * 16;

    #pragma unroll
    for (int i = 0; i < 16; i++)
        Ws[tid + i * 256] = W[tid + i * 256];

    #pragma unroll
    for (int i = 0; i < 4; i++) {
        int idx = tid + i * 256;
        int r = idx >> 6, c = idx & 63;
        int grow = row0 + r;
        Xs[r][c] = (grow < NN) ? X[grow * 64 + c] : 0.0f;
    }
    __syncthreads();

    #pragma unroll
    for (int rr = 0; rr < 4; rr++) {
        int r = ty + rr * 4;
        int grow = row0 + r;
        if (grow >= NN) continue;
        float acc = 0.0f;
        #pragma unroll
        for (int k = 0; k < 64; k++)
            acc = fmaf(Xs[r][k], Ws[k * 64 + tx], acc);
        float v = acc * rsqrtf(d_deg[grow] + 1.0f);
        d_gbuf[grow * 64 + tx] = v;
        d_accbuf[grow * 64 + tx] = v;
    }
}

// ---------------------------------------------------------------------------
// one thread per (edge, 4-channel chunk): acc[dst] += g[src]
__global__ void k_scatter(const int* __restrict__ edge_index) {
    long long id = (long long)blockIdx.x * blockDim.x + threadIdx.x;
    if (id >= (long long)EE * 16) return;
    int e = (int)(id >> 4);
    int q = (int)(id & 15);

    int src = edge_index[e];
    int dst = edge_index[EE + e];
    if ((unsigned)src >= NN || (unsigned)dst >= NN) return;

    const float4 v = *reinterpret_cast<const float4*>(&d_gbuf[src * 64 + q * 4]);
    float* a = &d_accbuf[dst * 64 + q * 4];
    atomicAdd(a + 0, v.x);
    atomicAdd(a + 1, v.y);
    atomicAdd(a + 2, v.z);
    atomicAdd(a + 3, v.w);
}

// ---------------------------------------------------------------------------
// h = relu(acc * rsqrt(deg+1) + b[c])
__global__ void k_fin(const float* __restrict__ b) {
    int id = blockIdx.x * blockDim.x + threadIdx.x;
    if (id >= NN * HH) return;
    int n = id >> 6;
    int c = id & 63;
    float dinv = rsqrtf(d_deg[n] + 1.0f);
    float v = fmaf(d_accbuf[id], dinv, b[c]);
    d_hbuf[id] = fmaxf(v, 0.0f);
}

// ---------------------------------------------------------------------------
__global__ void k_zero_pool() {
    int i = blockIdx.x * blockDim.x + threadIdx.x;
    if (i < GG * HH) d_sums[i] = 0.0f;
    if (i < GG) d_cnts[i] = 0.0f;
}

__global__ void k_pool(const int* __restrict__ batch) {
    int id = blockIdx.x * blockDim.x + threadIdx.x;
    if (id >= NN * HH) return;
    int n = id >> 6;
    int c = id & 63;
    int g = batch[n];
    if ((unsigned)g >= GG) return;
    atomicAdd(&d_sums[g * 64 + c], d_hbuf[id]);
    if (c == 0) atomicAdd(&d_cnts[g], 1.0f);
}

__global__ void k_final(const float* __restrict__ Wlin,
                        const float* __restrict__ blin,
                        float* __restrict__ out) {
    int t = threadIdx.x;
    if (t < GG * CC) {
        int g = t / CC, c = t % CC;
        float inv = 1.0f / fmaxf(d_cnts[g], 1.0f);
        float acc = blin[c];
        #pragma unroll
        for (int h = 0; h < HH; h++)
            acc = fmaf(d_sums[g * 64 + h] * inv, Wlin[h * CC + c], acc);
        out[g * CC + c] = acc;
    }
}

// ---------------------------------------------------------------------------
extern "C" void kernel_launch(void* const* d_in, const int* in_sizes, int n_in,
                              void* d_out, int out_size) {
    const float* x    = (const float*)d_in[0];
    const int*   ei   = (const int*)  d_in[1];
    const int*   batch= (const int*)  d_in[2];
    const float* W0   = (const float*)d_in[3];
    const float* b0   = (const float*)d_in[4];
    const float* W1   = (const float*)d_in[5];
    const float* b1   = (const float*)d_in[6];
    const float* W2   = (const float*)d_in[7];
    const float* b2   = (const float*)d_in[8];
    const float* Wlin = (const float*)d_in[9];
    const float* blin = (const float*)d_in[10];
    float* out = (float*)d_out;

    const int gemmB  = (NN + 15) / 16;
    const int nodeB  = (NN + 255) / 256;
    const int nodeNH = (NN * HH + 255) / 256;
    const int edgeB  = (EE + 255) / 256;
    const int scatB  = (int)(((long long)EE * 16 + 255) / 256);

    k_zero_deg<<<nodeB, 256>>>();
    k_deg<<<edgeB, 256>>>(ei);

    // layer 0 (input = x)
    k_gemm<false><<<gemmB, 256>>>(x, W0);
    k_scatter<<<scatB, 256>>>(ei);
    k_fin<<<nodeNH, 256>>>(b0);

    // layer 1 (input = d_hbuf, read device-side)
    k_gemm<true><<<gemmB, 256>>>(nullptr, W1);
    k_scatter<<<scatB, 256>>>(ei);
    k_fin<<<nodeNH, 256>>>(b1);

    // layer 2
    k_gemm<true><<<gemmB, 256>>>(nullptr, W2);
    k_scatter<<<scatB, 256>>>(ei);
    k_fin<<<nodeNH, 256>>>(b2);

    // pooling + head
    k_zero_pool<<<(GG * HH + 255) / 256, 256>>>();
    k_pool<<<nodeNH, 256>>>(batch);
    k_final<<<1, 128>>>(Wlin, blin, out);
}

// round 12
// speedup vs baseline: 2.8695x; 2.8695x over previous
#include <cuda_runtime.h>

#define NN 100000
#define EE 1600000
#define DD 64
#define HH 64
#define GG 64
#define CC 2

// ---- scratch (device globals; referenced ONLY inside device code) ----
__device__ __align__(16) float d_gbuf[NN * HH];   // scatter source
__device__ __align__(16) float d_accbuf[NN * HH]; // accumulator
__device__ float d_deg[NN];
__device__ float d_sums[GG * HH];
__device__ float d_cnts[GG];

// ---------------------------------------------------------------------------
__global__ void k_zero_deg() {
    int i = blockIdx.x * blockDim.x + threadIdx.x;
    if (i < NN) d_deg[i] = 0.0f;
}

__global__ void k_deg(const int* __restrict__ edge_index) {
    int e = blockIdx.x * blockDim.x + threadIdx.x;
    if (e < EE) {
        int dst = edge_index[EE + e];
        if ((unsigned)dst < NN) atomicAdd(&d_deg[dst], 1.0f);
    }
}

// ---------------------------------------------------------------------------
// Fused GEMM: X = FIRST ? Xext : relu(acc*dinv + b_prev)   (fin fused in)
// g[row] = (X[row] @ W) * rsqrt(deg+1);  acc[row] = g[row] (self-loop seed)
// 256 threads, 64 rows/block, 4x4 register tile per thread.
template <bool FIRST>
__global__ void k_gemm(const float* __restrict__ Xext,
                       const float* __restrict__ W,
                       const float* __restrict__ bprev) {
    __shared__ float Xs[64][65];      // padded: kills 2-way conflicts
    __shared__ __align__(16) float Ws[64 * 64];

    int tid = threadIdx.x;
    int row0 = blockIdx.x * 64;

    // load W (4096 floats, 16/thread)
    #pragma unroll
    for (int i = 0; i < 16; i++)
        Ws[tid + i * 256] = W[tid + i * 256];

    // stage X (64 rows x 64 cols), applying previous layer's finalize inline
    #pragma unroll
    for (int i = 0; i < 16; i++) {
        int idx = tid + i * 256;      // 0..4095
        int r = idx >> 6, c = idx & 63;
        int grow = row0 + r;
        float v = 0.0f;
        if (grow < NN) {
            if (FIRST) {
                v = Xext[grow * 64 + c];
            } else {
                float dinv = rsqrtf(d_deg[grow] + 1.0f);
                v = fmaxf(fmaf(d_accbuf[grow * 64 + c], dinv, bprev[c]), 0.0f);
            }
        }
        Xs[r][c] = v;
    }
    __syncthreads();

    int txg = tid & 15;               // column group: cols [txg*4, txg*4+4)
    int ty  = tid >> 4;               // row group: rows [ty*4, ty*4+4)

    float a0x = 0, a0y = 0, a0z = 0, a0w = 0;
    float a1x = 0, a1y = 0, a1z = 0, a1w = 0;
    float a2x = 0, a2y = 0, a2z = 0, a2w = 0;
    float a3x = 0, a3y = 0, a3z = 0, a3w = 0;

    #pragma unroll
    for (int k = 0; k < 64; k++) {
        float4 w = reinterpret_cast<const float4*>(Ws)[k * 16 + txg];
        float x0 = Xs[ty * 4 + 0][k];
        float x1 = Xs[ty * 4 + 1][k];
        float x2 = Xs[ty * 4 + 2][k];
        float x3 = Xs[ty * 4 + 3][k];
        a0x = fmaf(x0, w.x, a0x); a0y = fmaf(x0, w.y, a0y);
        a0z = fmaf(x0, w.z, a0z); a0w = fmaf(x0, w.w, a0w);
        a1x = fmaf(x1, w.x, a1x); a1y = fmaf(x1, w.y, a1y);
        a1z = fmaf(x1, w.z, a1z); a1w = fmaf(x1, w.w, a1w);
        a2x = fmaf(x2, w.x, a2x); a2y = fmaf(x2, w.y, a2y);
        a2z = fmaf(x2, w.z, a2z); a2w = fmaf(x2, w.w, a2w);
        a3x = fmaf(x3, w.x, a3x); a3y = fmaf(x3, w.y, a3y);
        a3z = fmaf(x3, w.z, a3z); a3w = fmaf(x3, w.w, a3w);
    }

    #pragma unroll
    for (int r = 0; r < 4; r++) {
        int grow = row0 + ty * 4 + r;
        if (grow >= NN) continue;
        float dinv = rsqrtf(d_deg[grow] + 1.0f);
        float4 v;
        if (r == 0) v = make_float4(a0x, a0y, a0z, a0w);
        else if (r == 1) v = make_float4(a1x, a1y, a1z, a1w);
        else if (r == 2) v = make_float4(a2x, a2y, a2z, a2w);
        else v = make_float4(a3x, a3y, a3z, a3w);
        v.x *= dinv; v.y *= dinv; v.z *= dinv; v.w *= dinv;
        long long off = (long long)grow * 16 + txg;
        reinterpret_cast<float4*>(d_gbuf)[off] = v;
        reinterpret_cast<float4*>(d_accbuf)[off] = v;
    }
}

// ---------------------------------------------------------------------------
// one thread per (edge, 16B chunk): acc[dst] += g[src] via vector reduction
__global__ void k_scatter(const int* __restrict__ edge_index) {
    int id = blockIdx.x * blockDim.x + threadIdx.x;   // < EE*16 = 25.6M
    if (id >= EE * 16) return;
    int e = id >> 4;
    int q = id & 15;

    int src = edge_index[e];
    int dst = edge_index[EE + e];
    if ((unsigned)src >= NN || (unsigned)dst >= NN) return;

    float4 v = reinterpret_cast<const float4*>(d_gbuf)[src * 16 + q];
    float* a = &d_accbuf[dst * 64 + q * 4];
    asm volatile("red.global.add.v4.f32 [%0], {%1, %2, %3, %4};"
                 :: "l"(a), "f"(v.x), "f"(v.y), "f"(v.z), "f"(v.w)
                 : "memory");
}

// ---------------------------------------------------------------------------
__global__ void k_zero_pool() {
    int i = blockIdx.x * blockDim.x + threadIdx.x;
    if (i < GG * HH) d_sums[i] = 0.0f;
    if (i < GG) d_cnts[i] = 0.0f;
}

// Fused finalize(layer2) + mean-pool numerators. Each thread: one column,
// 16 consecutive nodes; run-accumulate per graph (batch is sorted) and
// flush one atomic per run -> ~16x fewer atomics than per-element.
#define POOL_NPT 16
__global__ void k_pool(const int* __restrict__ batch,
                       const float* __restrict__ b2) {
    int t = blockIdx.x * blockDim.x + threadIdx.x;  // < (NN/16+1)*64
    int c = t & 63;
    int nb = t >> 6;
    int n0 = nb * POOL_NPT;
    if (n0 >= NN) return;

    int cur = -1;
    float s = 0.0f;
    float cnt = 0.0f;
    #pragma unroll
    for (int i = 0; i < POOL_NPT; i++) {
        int n = n0 + i;
        if (n >= NN) break;
        int g = batch[n];
        if (g != cur) {
            if (cur >= 0 && (unsigned)cur < GG) {
                atomicAdd(&d_sums[cur * 64 + c], s);
                if (c == 0) atomicAdd(&d_cnts[cur], cnt);
            }
            cur = g; s = 0.0f; cnt = 0.0f;
        }
        float dinv = rsqrtf(d_deg[n] + 1.0f);
        float h = fmaxf(fmaf(d_accbuf[n * 64 + c], dinv, b2[c]), 0.0f);
        s += h;
        cnt += 1.0f;
    }
    if (cur >= 0 && (unsigned)cur < GG) {
        atomicAdd(&d_sums[cur * 64 + c], s);
        if (c == 0) atomicAdd(&d_cnts[cur], cnt);
    }
}

__global__ void k_final(const float* __restrict__ Wlin,
                        const float* __restrict__ blin,
                        float* __restrict__ out) {
    int t = threadIdx.x;
    if (t < GG * CC) {
        int g = t / CC, c = t % CC;
        float inv = 1.0f / fmaxf(d_cnts[g], 1.0f);
        float acc = blin[c];
        #pragma unroll
        for (int h = 0; h < HH; h++)
            acc = fmaf(d_sums[g * 64 + h] * inv, Wlin[h * CC + c], acc);
        out[g * CC + c] = acc;
    }
}

// ---------------------------------------------------------------------------
extern "C" void kernel_launch(void* const* d_in, const int* in_sizes, int n_in,
                              void* d_out, int out_size) {
    const float* x    = (const float*)d_in[0];
    const int*   ei   = (const int*)  d_in[1];
    const int*   batch= (const int*)  d_in[2];
    const float* W0   = (const float*)d_in[3];
    const float* b0   = (const float*)d_in[4];
    const float* W1   = (const float*)d_in[5];
    const float* b1   = (const float*)d_in[6];
    const float* W2   = (const float*)d_in[7];
    const float* b2   = (const float*)d_in[8];
    const float* Wlin = (const float*)d_in[9];
    const float* blin = (const float*)d_in[10];
    float* out = (float*)d_out;

    const int gemmB = (NN + 63) / 64;                         // 1563
    const int nodeB = (NN + 255) / 256;
    const int edgeB = (EE + 255) / 256;
    const int scatB = (EE * 16 + 255) / 256;                  // 100000
    const int poolB = (((NN + POOL_NPT - 1) / POOL_NPT) * 64 + 255) / 256;

    k_zero_deg<<<nodeB, 256>>>();
    k_deg<<<edgeB, 256>>>(ei);

    // layer 0
    k_gemm<true><<<gemmB, 256>>>(x, W0, nullptr);
    k_scatter<<<scatB, 256>>>(ei);

    // layer 1 (finalize of layer 0 fused into the X staging)
    k_gemm<false><<<gemmB, 256>>>(nullptr, W1, b0);
    k_scatter<<<scatB, 256>>>(ei);

    // layer 2
    k_gemm<false><<<gemmB, 256>>>(nullptr, W2, b1);
    k_scatter<<<scatB, 256>>>(ei);

    // pooling (finalize of layer 2 fused) + head
    k_zero_pool<<<(GG * HH + 255) / 256, 256>>>();
    k_pool<<<poolB, 256>>>(batch, b2);
    k_final<<<1, 128>>>(Wlin, blin, out);
}